// round 13
// baseline (speedup 1.0000x reference)
#include <cuda_runtime.h>
#include <cuda_fp16.h>
#include <stdint.h>
#include <math.h>

// ---------------------------------------------------------------------------
// Problem constants (B=1)
// ---------------------------------------------------------------------------
#define T_SEQ 2048
#define D_MODEL 4096
#define KV_DIM 1024
#define HEAD_DIM 128
#define N_HEADS 32

#define GTHREADS 512            // projection GEMMs: 16 warps
#define BK2 64
#define ROWB2 144               // 64 halves (128B) + 16B pad
#define STG2 55296              // 384 rows * 144 B
#define SMEM_NT2 (4 * STG2)     // 221184

// Flash attention
#define FL_THREADS 256          // 8 warps, 16 q-rows each
#define FROW 272                // 128 halves + 16B pad
#define QBYTES (128 * FROW)     // 34816
#define KVST (2 * 128 * FROW)   // K tile + V tile per stage = 69632
#define SMEM_FL (QBYTES + 2 * KVST)   // 174080

#define LOG2E 1.4426950408889634f

// ---------------------------------------------------------------------------
// Scratch
// ---------------------------------------------------------------------------
__device__ __half g_xh[T_SEQ * D_MODEL];
__device__ __half g_wqh[D_MODEL * D_MODEL];
__device__ __half g_wkh[KV_DIM * D_MODEL];
__device__ __half g_wvh[KV_DIM * D_MODEL];
__device__ __half g_woh[D_MODEL * D_MODEL];
__device__ __half g_qh[T_SEQ * D_MODEL];
__device__ __half g_kh[T_SEQ * KV_DIM];
__device__ __half g_vh[T_SEQ * KV_DIM];
__device__ __half g_yh[T_SEQ * D_MODEL];

// ---------------------------------------------------------------------------
// Helpers
// ---------------------------------------------------------------------------
__device__ __forceinline__ uint32_t smem_u32(const void* p) {
    uint32_t a;
    asm("{ .reg .u64 t; cvta.to.shared.u64 t, %1; cvt.u32.u64 %0, t; }"
        : "=r"(a) : "l"(p));
    return a;
}

__device__ __forceinline__ void cp16(uint32_t dst, const void* src) {
    asm volatile("cp.async.cg.shared.global [%0], [%1], 16;" :: "r"(dst), "l"(src));
}
#define CP_COMMIT() asm volatile("cp.async.commit_group;" ::: "memory")
#define CP_WAIT(n)  asm volatile("cp.async.wait_group %0;" :: "n"(n) : "memory")

__device__ __forceinline__ uint32_t pk(float lo, float hi) {
    uint32_t r;
    asm("cvt.rn.f16x2.f32 %0, %1, %2;" : "=r"(r) : "f"(hi), "f"(lo));
    return r;
}

__device__ __forceinline__ uint32_t ex2h2(uint32_t x) {
    uint32_t r;
    asm("ex2.approx.f16x2 %0, %1;" : "=r"(r) : "r"(x));
    return r;
}

__device__ __forceinline__ void ldsm4(uint32_t& r0, uint32_t& r1, uint32_t& r2,
                                      uint32_t& r3, uint32_t a) {
    asm volatile("ldmatrix.sync.aligned.m8n8.x4.shared.b16 {%0,%1,%2,%3}, [%4];"
                 : "=r"(r0), "=r"(r1), "=r"(r2), "=r"(r3) : "r"(a));
}
__device__ __forceinline__ void ldsm4t(uint32_t& r0, uint32_t& r1, uint32_t& r2,
                                       uint32_t& r3, uint32_t a) {
    asm volatile("ldmatrix.sync.aligned.m8n8.x4.trans.shared.b16 {%0,%1,%2,%3}, [%4];"
                 : "=r"(r0), "=r"(r1), "=r"(r2), "=r"(r3) : "r"(a));
}

__device__ __forceinline__ void mma16816(float* d, uint32_t a0, uint32_t a1,
                                         uint32_t a2, uint32_t a3,
                                         uint32_t b0, uint32_t b1) {
    asm volatile(
        "mma.sync.aligned.m16n8k16.row.col.f32.f16.f16.f32 "
        "{%0,%1,%2,%3},{%4,%5,%6,%7},{%8,%9},{%0,%1,%2,%3};"
        : "+f"(d[0]), "+f"(d[1]), "+f"(d[2]), "+f"(d[3])
        : "r"(a0), "r"(a1), "r"(a2), "r"(a3), "r"(b0), "r"(b1));
}

// ---------------------------------------------------------------------------
// Projection GEMM: CTA tile [128,256], BK=64, 4-stage cp.async ring, 16 warps
// ---------------------------------------------------------------------------
__device__ __forceinline__ void stage_nt64(uint32_t dst, const __half* __restrict__ A,
                                           int lda, const __half* __restrict__ B,
                                           int ldb, int k0, int tid)
{
#pragma unroll
    for (int it = 0; it < 6; ++it) {
        int c = tid + it * GTHREADS;          // 0..3071
        int row = c >> 3;                     // 0..383
        int ch = c & 7;
        const __half* src = (row < 128)
            ? (A + (size_t)row * lda + k0 + ch * 8)
            : (B + (size_t)(row - 128) * ldb + k0 + ch * 8);
        cp16(dst + row * ROWB2 + ch * 16, src);
    }
}

__device__ __forceinline__ void mma32x64_k64(uint32_t sa, uint32_t sbb, int wm, int wn,
                                             int lane, float acc[2][8][4])
{
    const int sub = lane >> 3, rr = lane & 7;
    const uint32_t loff = ((sub & 1) * 8 + rr) * ROWB2 + (sub >> 1) * 16;
#pragma unroll
    for (int kk = 0; kk < 4; ++kk) {
        uint32_t a[2][4];
#pragma unroll
        for (int i = 0; i < 2; ++i)
            ldsm4(a[i][0], a[i][1], a[i][2], a[i][3],
                  sa + (wm * 32 + i * 16) * ROWB2 + kk * 32 + loff);
        uint32_t b[4][4];
#pragma unroll
        for (int jj = 0; jj < 4; ++jj)
            ldsm4(b[jj][0], b[jj][1], b[jj][2], b[jj][3],
                  sbb + (wn * 64 + jj * 16) * ROWB2 + kk * 32 + loff);
#pragma unroll
        for (int i = 0; i < 2; ++i)
#pragma unroll
            for (int jj = 0; jj < 4; ++jj) {
                mma16816(acc[i][jj * 2],     a[i][0], a[i][1], a[i][2], a[i][3],
                         b[jj][0], b[jj][2]);
                mma16816(acc[i][jj * 2 + 1], a[i][0], a[i][1], a[i][2], a[i][3],
                         b[jj][1], b[jj][3]);
            }
    }
}

// MODE: 0 = fp32 out, 1 = fp16 out, 2 = fp16 out with fused RoPE
template<int MODE>
__device__ __forceinline__ void store_acc32(void* Cv, int ldc,
                                            int row_base, int col_base,
                                            int wm, int wn, int lane,
                                            float acc[2][8][4],
                                            const float* __restrict__ cosp,
                                            const float* __restrict__ sinp)
{
    const int g = lane >> 2;
    const int t = lane & 3;
#pragma unroll
    for (int i = 0; i < 2; ++i) {
#pragma unroll
        for (int j = 0; j < 8; ++j) {
            int r = row_base + wm * 32 + i * 16 + g;
            int c = col_base + wn * 64 + j * 8 + t * 2;
            if (MODE == 0) {
                float* C = (float*)Cv;
                *(float2*)(C + (size_t)r * ldc + c) =
                    make_float2(acc[i][j][0], acc[i][j][1]);
                *(float2*)(C + (size_t)(r + 8) * ldc + c) =
                    make_float2(acc[i][j][2], acc[i][j][3]);
            } else if (MODE == 1) {
                __half* C = (__half*)Cv;
                *(__half2*)(C + (size_t)r * ldc + c) =
                    __floats2half2_rn(acc[i][j][0], acc[i][j][1]);
                *(__half2*)(C + (size_t)(r + 8) * ldc + c) =
                    __floats2half2_rn(acc[i][j][2], acc[i][j][3]);
            } else {
                __half* C = (__half*)Cv;
                int p = (c & (HEAD_DIM - 1)) >> 1;
                float c0 = cosp[r * 64 + p],       s0 = sinp[r * 64 + p];
                float c1 = cosp[(r + 8) * 64 + p], s1 = sinp[(r + 8) * 64 + p];
                float x1 = acc[i][j][0], x2 = acc[i][j][1];
                *(__half2*)(C + (size_t)r * ldc + c) =
                    __floats2half2_rn(x1 * c0 - x2 * s0, x1 * s0 + x2 * c0);
                x1 = acc[i][j][2]; x2 = acc[i][j][3];
                *(__half2*)(C + (size_t)(r + 8) * ldc + c) =
                    __floats2half2_rn(x1 * c1 - x2 * s1, x1 * s1 + x2 * c1);
            }
        }
    }
}

template<int MODE>
__device__ __forceinline__ void gemm_core64(const __half* Ab, const __half* Bb,
                                            void* C, int K, int lda, int ldb,
                                            int ldc, int row_base, int col_base,
                                            const float* cosp, const float* sinp,
                                            char* sm, int tid)
{
    const uint32_t sb = smem_u32(sm);
    const int lane = tid & 31, wid = tid >> 5;
    const int wm = wid & 3, wn = wid >> 2;

    float acc[2][8][4];
#pragma unroll
    for (int i = 0; i < 2; ++i)
#pragma unroll
        for (int j = 0; j < 8; ++j)
#pragma unroll
            for (int r = 0; r < 4; ++r) acc[i][j][r] = 0.f;

    const int NK = K / BK2;

#pragma unroll
    for (int s = 0; s < 3; ++s) {
        stage_nt64(sb + s * STG2, Ab, lda, Bb, ldb, s * BK2, tid);
        CP_COMMIT();
    }

    for (int kt = 0; kt < NK; ++kt) {
        CP_WAIT(2);
        __syncthreads();
        if (kt + 3 < NK)
            stage_nt64(sb + ((kt + 3) & 3) * STG2, Ab, lda, Bb, ldb, (kt + 3) * BK2, tid);
        CP_COMMIT();
        const uint32_t s = sb + (kt & 3) * STG2;
        mma32x64_k64(s, s + 128 * ROWB2, wm, wn, lane, acc);
    }
    store_acc32<MODE>(C, ldc, row_base, col_base, wm, wn, lane, acc, cosp, sinp);
}

// q + k + v in one launch: tiles 0..255 = q, 256..319 = k, 320..383 = v
__global__ __launch_bounds__(GTHREADS)
void gemm_h_qkv(const __half* __restrict__ X,
                const __half* __restrict__ Wq, const __half* __restrict__ Wk,
                const __half* __restrict__ Wv,
                __half* __restrict__ Qo, __half* __restrict__ Ko,
                __half* __restrict__ Vo,
                const float* __restrict__ cosp, const float* __restrict__ sinp)
{
    extern __shared__ char sm[];
    const int id = blockIdx.x;
    if (id < 256) {
        int xb = id & 15, yb = id >> 4;
        gemm_core64<2>(X + (size_t)yb * 128 * D_MODEL,
                       Wq + (size_t)xb * 256 * D_MODEL,
                       Qo, D_MODEL, D_MODEL, D_MODEL, D_MODEL,
                       yb * 128, xb * 256, cosp, sinp, sm, threadIdx.x);
    } else {
        int id2 = id - 256;
        int which = id2 >> 6;           // 0 = k, 1 = v
        int rem = id2 & 63;
        int xb = rem & 3, yb = rem >> 2;
        const __half* Xb = X + (size_t)yb * 128 * D_MODEL;
        if (which == 0)
            gemm_core64<2>(Xb, Wk + (size_t)xb * 256 * D_MODEL,
                           Ko, D_MODEL, D_MODEL, D_MODEL, KV_DIM,
                           yb * 128, xb * 256, cosp, sinp, sm, threadIdx.x);
        else
            gemm_core64<1>(Xb, Wv + (size_t)xb * 256 * D_MODEL,
                           Vo, D_MODEL, D_MODEL, D_MODEL, KV_DIM,
                           yb * 128, xb * 256, nullptr, nullptr, sm, threadIdx.x);
    }
}

__global__ __launch_bounds__(GTHREADS)
void gemm_h_o(const __half* __restrict__ Y, const __half* __restrict__ W,
              float* __restrict__ C)
{
    extern __shared__ char sm[];
    gemm_core64<0>(Y + (size_t)blockIdx.y * 128 * D_MODEL,
                   W + (size_t)blockIdx.x * 256 * D_MODEL,
                   C, D_MODEL, D_MODEL, D_MODEL, D_MODEL,
                   blockIdx.y * 128, blockIdx.x * 256, nullptr, nullptr, sm, threadIdx.x);
}

// ---------------------------------------------------------------------------
// Flash attention: one CTA = 128 q-rows of one head. fp16x2 exp.
// ---------------------------------------------------------------------------
__device__ __forceinline__ void stage_kv(uint32_t dst, const __half* __restrict__ K,
                                         const __half* __restrict__ V,
                                         int kv0, int kvh, int tid)
{
#pragma unroll
    for (int it = 0; it < 8; ++it) {
        int c = tid + it * FL_THREADS;
        int row = c >> 4, ch = c & 15;
        cp16(dst + row * FROW + ch * 16,
             K + (size_t)(kv0 + row) * KV_DIM + kvh * HEAD_DIM + ch * 8);
    }
#pragma unroll
    for (int it = 0; it < 8; ++it) {
        int c = tid + it * FL_THREADS;
        int row = c >> 4, ch = c & 15;
        cp16(dst + 128 * FROW + row * FROW + ch * 16,
             V + (size_t)(kv0 + row) * KV_DIM + kvh * HEAD_DIM + ch * 8);
    }
}

__global__ __launch_bounds__(FL_THREADS)
void flash_h(const __half* __restrict__ Q, const __half* __restrict__ K,
             const __half* __restrict__ V, __half* __restrict__ Y)
{
    extern __shared__ char sm[];
    const uint32_t sb = smem_u32(sm);
    const int h = blockIdx.y;
    const int qb = (int)(gridDim.x - 1 - blockIdx.x);   // heavy-first
    const int q0 = qb * 128;
    const int tid = threadIdx.x, lane = tid & 31, wq = tid >> 5;
    const int kvh = h >> 2;
    const int NB = qb + 1;

    {
#pragma unroll
        for (int it = 0; it < 8; ++it) {
            int c = tid + it * FL_THREADS;
            int row = c >> 4, ch = c & 15;
            cp16(sb + row * FROW + ch * 16,
                 Q + (size_t)(q0 + row) * D_MODEL + h * HEAD_DIM + ch * 8);
        }
        stage_kv(sb + QBYTES, K, V, 0, kvh, tid);
        CP_COMMIT();
    }
    if (NB > 1) {
        stage_kv(sb + QBYTES + KVST, K, V, 128, kvh, tid);
        CP_COMMIT();
        CP_WAIT(1);
    } else {
        CP_WAIT(0);
    }
    __syncthreads();

    const int sub = lane >> 3, rr = lane & 7;
    const uint32_t loff = ((sub & 1) * 8 + rr) * FROW + (sub >> 1) * 16;
    const int g = lane >> 2, t = lane & 3;
    const float scale = 0.08838834764831845f;

    uint32_t aq[8][4];
#pragma unroll
    for (int kc = 0; kc < 8; ++kc)
        ldsm4(aq[kc][0], aq[kc][1], aq[kc][2], aq[kc][3],
              sb + (wq * 16) * FROW + kc * 32 + loff);

    float m0 = -1e30f, m1 = -1e30f, l0 = 0.f, l1 = 0.f;
    float ao[16][4];
#pragma unroll
    for (int jt = 0; jt < 16; ++jt)
#pragma unroll
        for (int r = 0; r < 4; ++r) ao[jt][r] = 0.f;

    for (int kb = 0; kb < NB; ++kb) {
        const uint32_t kbase = sb + QBYTES + (kb & 1) * KVST;
        const uint32_t vbase = kbase + 128 * FROW;

        float sa[16][4];
#pragma unroll
        for (int jt = 0; jt < 16; ++jt)
#pragma unroll
            for (int r = 0; r < 4; ++r) sa[jt][r] = 0.f;
#pragma unroll
        for (int kc = 0; kc < 8; ++kc) {
#pragma unroll
            for (int nb = 0; nb < 8; ++nb) {
                uint32_t b0, b1, b2, b3;
                ldsm4(b0, b1, b2, b3, kbase + (nb * 16) * FROW + kc * 32 + loff);
                mma16816(sa[2 * nb],     aq[kc][0], aq[kc][1], aq[kc][2], aq[kc][3], b0, b2);
                mma16816(sa[2 * nb + 1], aq[kc][0], aq[kc][1], aq[kc][2], aq[kc][3], b1, b3);
            }
        }

        const int rA = wq * 16 + g, rB = rA + 8;
        if (kb == qb) {
#pragma unroll
            for (int jt = 0; jt < 16; ++jt) {
                int c0 = jt * 8 + 2 * t, c1 = c0 + 1;
                sa[jt][0] = (c0 > rA) ? -1e30f : sa[jt][0] * scale;
                sa[jt][1] = (c1 > rA) ? -1e30f : sa[jt][1] * scale;
                sa[jt][2] = (c0 > rB) ? -1e30f : sa[jt][2] * scale;
                sa[jt][3] = (c1 > rB) ? -1e30f : sa[jt][3] * scale;
            }
        } else {
#pragma unroll
            for (int jt = 0; jt < 16; ++jt)
#pragma unroll
                for (int r = 0; r < 4; ++r) sa[jt][r] *= scale;
        }

        float mx0 = -1e30f, mx1 = -1e30f;
#pragma unroll
        for (int jt = 0; jt < 16; ++jt) {
            mx0 = fmaxf(mx0, fmaxf(sa[jt][0], sa[jt][1]));
            mx1 = fmaxf(mx1, fmaxf(sa[jt][2], sa[jt][3]));
        }
        mx0 = fmaxf(mx0, __shfl_xor_sync(0xffffffffu, mx0, 1));
        mx0 = fmaxf(mx0, __shfl_xor_sync(0xffffffffu, mx0, 2));
        mx1 = fmaxf(mx1, __shfl_xor_sync(0xffffffffu, mx1, 1));
        mx1 = fmaxf(mx1, __shfl_xor_sync(0xffffffffu, mx1, 2));

        const float mN0 = fmaxf(m0, mx0);
        const float mN1 = fmaxf(m1, mx1);
        const float al0 = __expf(m0 - mN0);
        const float al1 = __expf(m1 - mN1);
        const float mNL0 = mN0 * LOG2E;
        const float mNL1 = mN1 * LOG2E;

        // ---- p = exp2((s - m)*log2e) computed directly in fp16x2 ----
        uint32_t pa[8][4];
        float s0 = 0.f, s1 = 0.f;
#pragma unroll
        for (int jt = 0; jt < 16; ++jt) {
            uint32_t e01 = ex2h2(pk(fmaf(sa[jt][0], LOG2E, -mNL0),
                                    fmaf(sa[jt][1], LOG2E, -mNL0)));
            uint32_t e23 = ex2h2(pk(fmaf(sa[jt][2], LOG2E, -mNL1),
                                    fmaf(sa[jt][3], LOG2E, -mNL1)));
            float2 f01 = __half22float2(*(__half2*)&e01);
            float2 f23 = __half22float2(*(__half2*)&e23);
            s0 += f01.x + f01.y;
            s1 += f23.x + f23.y;
            pa[jt >> 1][(jt & 1) * 2 + 0] = e01;
            pa[jt >> 1][(jt & 1) * 2 + 1] = e23;
        }
        s0 += __shfl_xor_sync(0xffffffffu, s0, 1);
        s0 += __shfl_xor_sync(0xffffffffu, s0, 2);
        s1 += __shfl_xor_sync(0xffffffffu, s1, 1);
        s1 += __shfl_xor_sync(0xffffffffu, s1, 2);

        l0 = l0 * al0 + s0;  m0 = mN0;
        l1 = l1 * al1 + s1;  m1 = mN1;

#pragma unroll
        for (int jt = 0; jt < 16; ++jt) {
            ao[jt][0] *= al0; ao[jt][1] *= al0;
            ao[jt][2] *= al1; ao[jt][3] *= al1;
        }

#pragma unroll
        for (int kc = 0; kc < 8; ++kc) {
#pragma unroll
            for (int nb = 0; nb < 8; ++nb) {
                uint32_t b0, b1, b2, b3;
                ldsm4t(b0, b1, b2, b3,
                       vbase + (kc * 16 + (sub >> 1) * 8 + rr) * FROW
                             + (nb * 16) * 2 + (sub & 1) * 16);
                mma16816(ao[2 * nb],     pa[kc][0], pa[kc][1], pa[kc][2], pa[kc][3], b0, b2);
                mma16816(ao[2 * nb + 1], pa[kc][0], pa[kc][1], pa[kc][2], pa[kc][3], b1, b3);
            }
        }

        if (kb + 1 < NB) {
            __syncthreads();
            if (kb + 2 < NB) {
                stage_kv(sb + QBYTES + (kb & 1) * KVST, K, V, (kb + 2) * 128, kvh, tid);
                CP_COMMIT();
                CP_WAIT(1);
            } else {
                CP_WAIT(0);
            }
            __syncthreads();
        }
    }

    const float i0 = 1.f / l0, i1 = 1.f / l1;
    const int rowA = q0 + wq * 16 + g;
    __half* yr = Y + (size_t)rowA * D_MODEL + h * HEAD_DIM;
#pragma unroll
    for (int jt = 0; jt < 16; ++jt) {
        int col = jt * 8 + t * 2;
        *(__half2*)(yr + col) = __floats2half2_rn(ao[jt][0] * i0, ao[jt][1] * i0);
        *(__half2*)(yr + 8 * D_MODEL + col) = __floats2half2_rn(ao[jt][2] * i1, ao[jt][3] * i1);
    }
}

// ---------------------------------------------------------------------------
// fp32 -> fp16 convert, all five arrays in one launch (grid.y selects array)
// ---------------------------------------------------------------------------
__global__ __launch_bounds__(256)
void cvt_all(const float* __restrict__ x,  const float* __restrict__ wq,
             const float* __restrict__ wk, const float* __restrict__ wv,
             const float* __restrict__ wo,
             __half* __restrict__ xh,  __half* __restrict__ wqh,
             __half* __restrict__ wkh, __half* __restrict__ wvh,
             __half* __restrict__ woh)
{
    const float* in; __half* out; int n4;
    switch (blockIdx.y) {
        case 0: in = x;  out = xh;  n4 = T_SEQ * D_MODEL / 4;   break;
        case 1: in = wq; out = wqh; n4 = D_MODEL * D_MODEL / 4; break;
        case 2: in = wk; out = wkh; n4 = KV_DIM * D_MODEL / 4;  break;
        case 3: in = wv; out = wvh; n4 = KV_DIM * D_MODEL / 4;  break;
        default: in = wo; out = woh; n4 = D_MODEL * D_MODEL / 4; break;
    }
    int i = blockIdx.x * 256 + threadIdx.x;
    if (i < n4) {
        float4 v = ((const float4*)in)[i];
        ((__half2*)out)[i * 2]     = __floats2half2_rn(v.x, v.y);
        ((__half2*)out)[i * 2 + 1] = __floats2half2_rn(v.z, v.w);
    }
}

// ---------------------------------------------------------------------------
// Launch
// ---------------------------------------------------------------------------
extern "C" void kernel_launch(void* const* d_in, const int* in_sizes, int n_in,
                              void* d_out, int out_size)
{
    const float* x    = (const float*)d_in[0];
    const float* cosp = (const float*)d_in[1];
    const float* sinp = (const float*)d_in[2];
    const float* wq   = (const float*)d_in[3];
    const float* wk   = (const float*)d_in[4];
    const float* wv   = (const float*)d_in[5];
    const float* wo   = (const float*)d_in[6];
    float* out = (float*)d_out;

    __half *xh, *wqh, *wkh, *wvh, *woh, *qh, *kh, *vh, *yh;
    cudaGetSymbolAddress((void**)&xh,  g_xh);
    cudaGetSymbolAddress((void**)&wqh, g_wqh);
    cudaGetSymbolAddress((void**)&wkh, g_wkh);
    cudaGetSymbolAddress((void**)&wvh, g_wvh);
    cudaGetSymbolAddress((void**)&woh, g_woh);
    cudaGetSymbolAddress((void**)&qh,  g_qh);
    cudaGetSymbolAddress((void**)&kh,  g_kh);
    cudaGetSymbolAddress((void**)&vh,  g_vh);
    cudaGetSymbolAddress((void**)&yh,  g_yh);

    cudaFuncSetAttribute(gemm_h_qkv, cudaFuncAttributeMaxDynamicSharedMemorySize, SMEM_NT2);
    cudaFuncSetAttribute(gemm_h_o,   cudaFuncAttributeMaxDynamicSharedMemorySize, SMEM_NT2);
    cudaFuncSetAttribute(flash_h,    cudaFuncAttributeMaxDynamicSharedMemorySize, SMEM_FL);

    // converts (one launch)
    cvt_all<<<dim3((D_MODEL * D_MODEL / 4 + 255) / 256, 5), 256>>>(
        x, wq, wk, wv, wo, xh, wqh, wkh, wvh, woh);

    // q/k/v projections + fused RoPE (one launch, 384 tiles)
    gemm_h_qkv<<<dim3(384), dim3(GTHREADS), SMEM_NT2>>>(
        xh, wqh, wkh, wvh, qh, kh, vh, cosp, sinp);

    flash_h<<<dim3(T_SEQ / 128, N_HEADS), dim3(FL_THREADS), SMEM_FL>>>(qh, kh, vh, yh);

    gemm_h_o<<<dim3(D_MODEL / 256, T_SEQ / 128), dim3(GTHREADS), SMEM_NT2>>>(yh, woh, out);
}